// round 4
// baseline (speedup 1.0000x reference)
#include <cuda_runtime.h>
#include <math.h>

#define B_ 4
#define N_ 4096
#define M_ 1024
#define C_ 384
#define H_ 8
#define HD_ 48

// Scratch (allocation-free rule: __device__ globals)
__device__ float g_q [B_ * (size_t)N_ * C_];       // q projection  [B,N,384]
__device__ float g_kv[B_ * (size_t)M_ * 2 * C_];   // kv projection [B,M,2,384]
__device__ float g_x [B_ * (size_t)N_ * C_];       // attention out [B,N,384]

// Packed fp32x2 FMA (sm_100+): FFMA2 — 2x fp32 throughput on fma pipe.
__device__ __forceinline__ float2 ffma2(float2 a, float2 b, float2 c) {
    unsigned long long au, bu, cu, du;
    au = *reinterpret_cast<unsigned long long*>(&a);
    bu = *reinterpret_cast<unsigned long long*>(&b);
    cu = *reinterpret_cast<unsigned long long*>(&c);
    asm("fma.rn.f32x2 %0, %1, %2, %3;" : "=l"(du) : "l"(au), "l"(bu), "l"(cu));
    return *reinterpret_cast<float2*>(&du);
}

__device__ __forceinline__ float ex2(float x) {
    float y;
    asm("ex2.approx.ftz.f32 %0, %1;" : "=f"(y) : "f"(x));
    return y;
}

// ---------------------------------------------------------------------------
// SGEMM: C[M,N] = A[M,K] @ B[K,N] (+ bias[n] + res[m,n] if EPI)
// BM=BN=128, BK=8, 256 threads, 8x8 micro-tile, FFMA2, reg prefetch.
// ---------------------------------------------------------------------------
template <bool EPI>
__global__ __launch_bounds__(256, 2) void sgemm128_kernel(
    const float* __restrict__ A, const float* __restrict__ Bm,
    float* __restrict__ C, int M, int N, int K,
    const float* __restrict__ bias, const float* __restrict__ res)
{
    const int BM = 128, BN = 128, BK = 8;
    __shared__ __align__(16) float As[BK][BM];
    __shared__ __align__(16) float Bs[BK][BN];

    const int tid = threadIdx.x;
    const int tx = tid & 15;
    const int ty = tid >> 4;
    const int rowBase = blockIdx.y * BM;
    const int colBase = blockIdx.x * BN;

    const int arow = tid >> 1;
    const int acol = (tid & 1) * 4;
    const int brow = tid >> 5;
    const int bcol = (tid & 31) * 4;

    const float* Aptr = A + (size_t)(rowBase + arow) * K + acol;
    const float* Bptr = Bm + (size_t)brow * N + colBase + bcol;

    float4 aReg = *reinterpret_cast<const float4*>(Aptr);
    float4 bReg = *reinterpret_cast<const float4*>(Bptr);

    float2 acc[8][4];
    #pragma unroll
    for (int i = 0; i < 8; i++)
        #pragma unroll
        for (int j = 0; j < 4; j++) acc[i][j] = make_float2(0.f, 0.f);

    for (int k0 = 0; k0 < K; k0 += BK) {
        __syncthreads();
        As[acol + 0][arow] = aReg.x;
        As[acol + 1][arow] = aReg.y;
        As[acol + 2][arow] = aReg.z;
        As[acol + 3][arow] = aReg.w;
        *reinterpret_cast<float4*>(&Bs[brow][bcol]) = bReg;
        __syncthreads();

        if (k0 + BK < K) {
            aReg = *reinterpret_cast<const float4*>(Aptr + k0 + BK);
            bReg = *reinterpret_cast<const float4*>(Bptr + (size_t)(k0 + BK) * N);
        }

        #pragma unroll
        for (int kk = 0; kk < BK; kk++) {
            float4 a0 = *reinterpret_cast<const float4*>(&As[kk][ty * 8]);
            float4 a1 = *reinterpret_cast<const float4*>(&As[kk][ty * 8 + 4]);
            float4 b0 = *reinterpret_cast<const float4*>(&Bs[kk][tx * 8]);
            float4 b1 = *reinterpret_cast<const float4*>(&Bs[kk][tx * 8 + 4]);
            float av[8] = {a0.x, a0.y, a0.z, a0.w, a1.x, a1.y, a1.z, a1.w};
            float2 bv[4] = {make_float2(b0.x, b0.y), make_float2(b0.z, b0.w),
                            make_float2(b1.x, b1.y), make_float2(b1.z, b1.w)};
            #pragma unroll
            for (int i = 0; i < 8; i++) {
                float2 ad = make_float2(av[i], av[i]);
                #pragma unroll
                for (int j = 0; j < 4; j++)
                    acc[i][j] = ffma2(ad, bv[j], acc[i][j]);
            }
        }
    }

    #pragma unroll
    for (int i = 0; i < 8; i++) {
        const int row = rowBase + ty * 8 + i;
        const int col = colBase + tx * 8;
        float4 v0 = make_float4(acc[i][0].x, acc[i][0].y, acc[i][1].x, acc[i][1].y);
        float4 v1 = make_float4(acc[i][2].x, acc[i][2].y, acc[i][3].x, acc[i][3].y);
        if (EPI) {
            float4 bz0 = *reinterpret_cast<const float4*>(&bias[col]);
            float4 bz1 = *reinterpret_cast<const float4*>(&bias[col + 4]);
            float4 rz0 = *reinterpret_cast<const float4*>(&res[(size_t)row * N + col]);
            float4 rz1 = *reinterpret_cast<const float4*>(&res[(size_t)row * N + col + 4]);
            v0.x += bz0.x + rz0.x; v0.y += bz0.y + rz0.y;
            v0.z += bz0.z + rz0.z; v0.w += bz0.w + rz0.w;
            v1.x += bz1.x + rz1.x; v1.y += bz1.y + rz1.y;
            v1.z += bz1.z + rz1.z; v1.w += bz1.w + rz1.w;
        }
        *reinterpret_cast<float4*>(&C[(size_t)row * N + col]) = v0;
        *reinterpret_cast<float4*>(&C[(size_t)row * N + col + 4]) = v1;
    }
}

// ---------------------------------------------------------------------------
// Block-GEMM flash attention.
// Block: 256 threads, 64 queries x one head. Chunks of 64 keys.
// Phase1: S = Q@K^T micro-GEMM (4x4/thread). Softmax: half-warp shuffles +
// per-row (m,l,corr) in smem. P staged in smem. Phase2: P@V micro-GEMM
// (2 rows x 6 cols per thread). All math FFMA2; exp in log2 domain.
//
// Dynamic smem layout (floats):
//   sQT  [48][64]   @ 0       (Q transposed, pre-scaled)
//   sKT  [48][64]   @ 3072
//   sV   [64][48]   @ 6144
//   sP   [64][68]   @ 9216    (also K/Q staging viewed as [64][49])
//   sM/sL/sC [64]x3 @ 13568
// total = 13760 floats = 55040 B
// ---------------------------------------------------------------------------
#define ATTN_SMEM_FLOATS 13760

__global__ __launch_bounds__(256) void attn_kernel(
    const float* __restrict__ q, const float* __restrict__ kv,
    float* __restrict__ x)
{
    extern __shared__ float sm[];
    float* sQT = sm;               // [48][64]
    float* sKT = sm + 3072;        // [48][64]
    float* sV  = sm + 6144;        // [64][48]
    float* sP  = sm + 9216;        // [64][68] / staging [64][49]
    float* sM  = sm + 13568;
    float* sL  = sm + 13568 + 64;
    float* sC  = sm + 13568 + 128;

    const int tid = threadIdx.x;
    const int b = blockIdx.z, h = blockIdx.y;
    const int n0 = blockIdx.x * 64;
    const int tx = tid & 15, ty = tid >> 4;    // phase1: 4 rows x 4 cols
    const int rtx = tid & 7, rty = tid >> 3;   // phase2: 2 rows x 6 cols
    const float qscale = 0.144337567297406441127f * 1.44269504088896340736f;

    // ---- Q tile: stage coalesced, transpose into sQT with pre-scale ----
    {
        const float* qbase = q + ((size_t)(b * N_ + n0)) * C_ + h * HD_;
        #pragma unroll
        for (int t = 0; t < 12; t++) {
            int idx = tid + t * 256;
            int r = idx / 48, d = idx - r * 48;
            sP[r * 49 + d] = qbase[(size_t)r * C_ + d];
        }
        if (tid < 64) { sM[tid] = -1e30f; sL[tid] = 0.f; }
    }
    __syncthreads();
    #pragma unroll
    for (int t = 0; t < 12; t++) {
        int idx = tid + t * 256;
        int j = idx & 63, d = idx >> 6;
        sQT[d * 64 + j] = sP[j * 49 + d] * qscale;
    }

    float2 acc[2][3];
    #pragma unroll
    for (int i = 0; i < 2; i++)
        #pragma unroll
        for (int c = 0; c < 3; c++) acc[i][c] = make_float2(0.f, 0.f);

    for (int m0 = 0; m0 < M_; m0 += 64) {
        __syncthreads();   // prior phase2 / Q-transpose complete before restage

        // ---- load K (staged) + V ----
        const float* kbase = kv + ((size_t)(b * M_ + m0)) * 2 * C_ + h * HD_;
        #pragma unroll
        for (int t = 0; t < 12; t++) {
            int idx = tid + t * 256;
            int r = idx / 48, d = idx - r * 48;
            const float* p = kbase + (size_t)r * 2 * C_ + d;
            sP[r * 49 + d] = p[0];
            sV[r * 48 + d] = p[C_];
        }
        __syncthreads();
        #pragma unroll
        for (int t = 0; t < 12; t++) {
            int idx = tid + t * 256;
            int j = idx & 63, d = idx >> 6;
            sKT[d * 64 + j] = sP[j * 49 + d];
        }
        __syncthreads();

        // ---- phase 1: S(4x4) = Q rows (ty*4..) x K cols (tx*4..) ----
        float2 s2[2][4];   // row pairs packed in lanes: .x=row 2rp, .y=row 2rp+1
        #pragma unroll
        for (int rp = 0; rp < 2; rp++)
            #pragma unroll
            for (int c = 0; c < 4; c++) s2[rp][c] = make_float2(0.f, 0.f);

        #pragma unroll 8
        for (int kk = 0; kk < 48; kk++) {
            float4 qf = *reinterpret_cast<const float4*>(&sQT[kk * 64 + ty * 4]);
            float4 kf = *reinterpret_cast<const float4*>(&sKT[kk * 64 + tx * 4]);
            float2 qa = make_float2(qf.x, qf.y);
            float2 qb = make_float2(qf.z, qf.w);
            float2 k0 = make_float2(kf.x, kf.x);
            float2 k1 = make_float2(kf.y, kf.y);
            float2 k2 = make_float2(kf.z, kf.z);
            float2 k3 = make_float2(kf.w, kf.w);
            s2[0][0] = ffma2(qa, k0, s2[0][0]);
            s2[0][1] = ffma2(qa, k1, s2[0][1]);
            s2[0][2] = ffma2(qa, k2, s2[0][2]);
            s2[0][3] = ffma2(qa, k3, s2[0][3]);
            s2[1][0] = ffma2(qb, k0, s2[1][0]);
            s2[1][1] = ffma2(qb, k1, s2[1][1]);
            s2[1][2] = ffma2(qb, k2, s2[1][2]);
            s2[1][3] = ffma2(qb, k3, s2[1][3]);
        }

        // ---- softmax (rows owned by half-warp: lanes tx=0..15) ----
        const float* sf = reinterpret_cast<const float*>(s2); // [rp][c][lane]
        #pragma unroll
        for (int i = 0; i < 4; i++) {
            const int r = ty * 4 + i;
            const int rp = i >> 1, lo = i & 1;
            float v0 = sf[rp * 8 + 0 + lo ? rp * 8 + 0 * 2 + lo : 0]; // (placeholder, real below)
            float a0 = sf[rp * 8 + 0 * 2 + lo];
            float a1 = sf[rp * 8 + 1 * 2 + lo];
            float a2 = sf[rp * 8 + 2 * 2 + lo];
            float a3 = sf[rp * 8 + 3 * 2 + lo];
            (void)v0;
            float mx = fmaxf(fmaxf(a0, a1), fmaxf(a2, a3));
            #pragma unroll
            for (int off = 8; off > 0; off >>= 1)
                mx = fmaxf(mx, __shfl_xor_sync(0xffffffffu, mx, off, 16));
            float mold = sM[r];
            float mnew = fmaxf(mold, mx);
            float corr = ex2(mold - mnew);
            float p0 = ex2(a0 - mnew);
            float p1 = ex2(a1 - mnew);
            float p2 = ex2(a2 - mnew);
            float p3 = ex2(a3 - mnew);
            float rsum = (p0 + p1) + (p2 + p3);
            #pragma unroll
            for (int off = 8; off > 0; off >>= 1)
                rsum += __shfl_xor_sync(0xffffffffu, rsum, off, 16);
            if (tx == 0) {
                sL[r] = sL[r] * corr + rsum;
                sM[r] = mnew;
                sC[r] = corr;
            }
            *reinterpret_cast<float4*>(&sP[r * 68 + tx * 4]) =
                make_float4(p0, p1, p2, p3);
        }
        __syncthreads();

        // ---- phase 2: acc(2x6) += P rows (rty*2..) @ V cols (rtx*6..) ----
        {
            const int r0 = rty * 2;
            float c0 = sC[r0], c1 = sC[r0 + 1];
            #pragma unroll
            for (int c = 0; c < 3; c++) {
                acc[0][c].x *= c0; acc[0][c].y *= c0;
                acc[1][c].x *= c1; acc[1][c].y *= c1;
            }
            #pragma unroll 8
            for (int j = 0; j < 64; j++) {
                float p0 = sP[r0 * 68 + j];
                float p1 = sP[(r0 + 1) * 68 + j];
                float2 p0d = make_float2(p0, p0);
                float2 p1d = make_float2(p1, p1);
                const float2* vv = reinterpret_cast<const float2*>(&sV[j * 48 + rtx * 6]);
                float2 v0 = vv[0], v1 = vv[1], v2 = vv[2];
                acc[0][0] = ffma2(p0d, v0, acc[0][0]);
                acc[0][1] = ffma2(p0d, v1, acc[0][1]);
                acc[0][2] = ffma2(p0d, v2, acc[0][2]);
                acc[1][0] = ffma2(p1d, v0, acc[1][0]);
                acc[1][1] = ffma2(p1d, v1, acc[1][1]);
                acc[1][2] = ffma2(p1d, v2, acc[1][2]);
            }
        }
    }

    // ---- normalize + store ----
    const int r0 = rty * 2;
    const float inv0 = 1.0f / sL[r0];
    const float inv1 = 1.0f / sL[r0 + 1];
    float* xp0 = x + ((size_t)(b * N_ + n0 + r0)) * C_ + h * HD_ + rtx * 6;
    float* xp1 = xp0 + C_;
    #pragma unroll
    for (int c = 0; c < 3; c++) {
        reinterpret_cast<float2*>(xp0)[c] =
            make_float2(acc[0][c].x * inv0, acc[0][c].y * inv0);
        reinterpret_cast<float2*>(xp1)[c] =
            make_float2(acc[1][c].x * inv1, acc[1][c].y * inv1);
    }
}

// ---------------------------------------------------------------------------
// Launch
// ---------------------------------------------------------------------------
extern "C" void kernel_launch(void* const* d_in, const int* in_sizes, int n_in,
                              void* d_out, int out_size)
{
    const float* q_x   = (const float*)d_in[0];  // [4,4096,384]
    const float* kv_x  = (const float*)d_in[1];  // [4,1024,384]
    const float* Wq    = (const float*)d_in[2];  // [384,384]
    const float* Wkv   = (const float*)d_in[3];  // [384,768]
    const float* Wproj = (const float*)d_in[4];  // [384,384]
    const float* bproj = (const float*)d_in[5];  // [384]
    float* out = (float*)d_out;                  // [4,4096,384]

    float *gq, *gkv, *gx;
    cudaGetSymbolAddress((void**)&gq,  g_q);
    cudaGetSymbolAddress((void**)&gkv, g_kv);
    cudaGetSymbolAddress((void**)&gx,  g_x);

    static bool attr_set = false;
    if (!attr_set) {
        cudaFuncSetAttribute(attn_kernel,
                             cudaFuncAttributeMaxDynamicSharedMemorySize,
                             ATTN_SMEM_FLOATS * 4);
        attr_set = true;
    }

    // 1) q = q_x @ Wq          [16384,384]
    sgemm128_kernel<false><<<dim3(C_ / 128, (B_ * N_) / 128), 256>>>(
        q_x, Wq, gq, B_ * N_, C_, C_, nullptr, nullptr);

    // 2) kv = kv_x @ Wkv       [4096,768]
    sgemm128_kernel<false><<<dim3((2 * C_) / 128, (B_ * M_) / 128), 256>>>(
        kv_x, Wkv, gkv, B_ * M_, 2 * C_, C_, nullptr, nullptr);

    // 3) attention -> g_x [B,N,384]
    attn_kernel<<<dim3(N_ / 64, H_, B_), 256, ATTN_SMEM_FLOATS * 4>>>(gq, gkv, gx);

    // 4) out = g_x @ Wproj + bproj + g_q
    sgemm128_kernel<true><<<dim3(C_ / 128, (B_ * N_) / 128), 256>>>(
        gx, Wproj, out, B_ * N_, C_, C_, bproj, gq);
}